// round 4
// baseline (speedup 1.0000x reference)
#include <cuda_runtime.h>

// ChamferDistanceLoss fused: ONE pass over all (n,m) pairs computes
// d' = ||p||^2 - 2 q.p (3 FFMA2 per query-pair per point) and feeds BOTH
// reductions: row-min per query (register FMNMX, + ||q||^2 at the end) and
// col-min per tile point (packed +||q||^2, FMNMX tree, REDUX warp min,
// lane0 atomicMin into shared). fma pipe is the roofline: (12 FFMA2 + 4
// FADD2) x rt4 = 64 cyc per warp-j covering 256 pairs.

#define PADV  10000.0f
#define TPB   128
#define QPT   8            // fg queries per thread (4 packed f32x2 pairs)
#define QPB   (TPB * QPT)  // 1024 queries per block
#define SPLIT 16           // m-slices per (n-chunk, b)
#define TILE  256
#define MAXB  8
#define MAXQ  4096
#define MAXX  8            // max n-chunks (N/QPB)
#define RCHUNK 4

static __device__ float    g_rowmin[SPLIT][MAXB][MAXQ];       // partial row mins (over m-slice)
static __device__ unsigned g_colmin[MAXX][MAXB][MAXQ];        // partial col mins (over n-chunk), float bits
static __device__ float    g_rsum[2][MAXB][RCHUNK];
static __device__ float    g_rcnt[MAXB][RCHUNK];

__device__ __forceinline__ unsigned long long ffma2(unsigned long long a,
                                                    unsigned long long b,
                                                    unsigned long long c) {
    unsigned long long d;
    asm("fma.rn.f32x2 %0, %1, %2, %3;" : "=l"(d) : "l"(a), "l"(b), "l"(c));
    return d;
}
__device__ __forceinline__ unsigned long long fadd2(unsigned long long a,
                                                    unsigned long long b) {
    unsigned long long d;
    asm("add.rn.f32x2 %0, %1, %2;" : "=l"(d) : "l"(a), "l"(b));
    return d;
}
__device__ __forceinline__ unsigned long long pack2(float lo, float hi) {
    unsigned long long d;
    asm("mov.b64 %0, {%1, %2};" : "=l"(d) : "f"(lo), "f"(hi));
    return d;
}
__device__ __forceinline__ void unpack2(unsigned long long v, float& lo, float& hi) {
    asm("mov.b64 {%0, %1}, %2;" : "=f"(lo), "=f"(hi) : "l"(v));
}

// grid: (N/QPB, B, SPLIT). x = n-chunk (queries), z = m-slice (tile points).
__global__ __launch_bounds__(TPB, 6) void nn_fused(const float* __restrict__ fg,
                                                   const float* __restrict__ prj,
                                                   int N, int M) {
    __shared__ __align__(16) unsigned long long s_tile[TILE][4];
    __shared__ unsigned s_cmin[TILE];

    int b  = blockIdx.y;
    int zs = blockIdx.z;
    int xc = blockIdx.x;

    // load 8 fg queries per thread, pack into 4 f32x2 pairs
    float qx[QPT], qy[QPT], qz[QPT], qn[QPT];
    int q0 = xc * QPB + threadIdx.x;
    #pragma unroll
    for (int k = 0; k < QPT; k++) {
        int qi = q0 + k * TPB;
        int qc = (qi < N) ? qi : 0;   // clamp: duplicate of point 0 can't change a min
        const float* p = fg + ((size_t)b * N + qc) * 3;
        qx[k] = p[0]; qy[k] = p[1]; qz[k] = p[2];
        qn[k] = qx[k]*qx[k] + qy[k]*qy[k] + qz[k]*qz[k];
    }
    unsigned long long ax[4], ay[4], az[4], qnp[4];
    #pragma unroll
    for (int j = 0; j < 4; j++) {
        ax[j]  = pack2(qx[2*j], qx[2*j+1]);
        ay[j]  = pack2(qy[2*j], qy[2*j+1]);
        az[j]  = pack2(qz[2*j], qz[2*j+1]);
        qnp[j] = pack2(qn[2*j], qn[2*j+1]);
    }

    float best[QPT];
    #pragma unroll
    for (int k = 0; k < QPT; k++) best[k] = 3.0e38f;

    int len = (M + SPLIT - 1) / SPLIT;
    int r0  = zs * len;
    int r1  = min(r0 + len, M);
    const float* rb = prj + (size_t)b * M * 3;

    for (int base = r0; base < r1; base += TILE) {
        int cnt = min(TILE, r1 - base);
        __syncthreads();  // protect previous tile + s_cmin readers
        for (int j = threadIdx.x; j < cnt; j += TPB) {
            const float* pp = rb + (size_t)(base + j) * 3;
            float px = pp[0], py = pp[1], pz = pp[2];
            float w = px*px + py*py + pz*pz;
            s_tile[j][0] = pack2(-2.f*px, -2.f*px);
            s_tile[j][1] = pack2(-2.f*py, -2.f*py);
            s_tile[j][2] = pack2(-2.f*pz, -2.f*pz);
            s_tile[j][3] = pack2(w, w);
            s_cmin[j] = 0x7F7FFFFFu;
        }
        __syncthreads();
        #pragma unroll 4
        for (int j = 0; j < cnt; j++) {
            ulonglong2 t01 = *reinterpret_cast<const ulonglong2*>(&s_tile[j][0]);
            ulonglong2 t23 = *reinterpret_cast<const ulonglong2*>(&s_tile[j][2]);
            float cmin_j = 3.0e38f;
            #pragma unroll
            for (int p2 = 0; p2 < 4; p2++) {
                unsigned long long d = ffma2(t23.x, az[p2], t23.y);
                d = ffma2(t01.y, ay[p2], d);
                d = ffma2(t01.x, ax[p2], d);
                float lo, hi;
                unpack2(d, lo, hi);
                best[2*p2]     = fminf(best[2*p2],     lo);
                best[2*p2 + 1] = fminf(best[2*p2 + 1], hi);
                // col candidate: full d2 = d' + ||q||^2 (packed add)
                unsigned long long c = fadd2(d, qnp[p2]);
                float clo, chi;
                unpack2(c, clo, chi);
                cmin_j = fminf(cmin_j, fminf(clo, chi));
            }
            unsigned u = __reduce_min_sync(0xFFFFFFFFu, __float_as_uint(cmin_j));
            if ((threadIdx.x & 31) == 0) atomicMin(&s_cmin[j], u);
        }
        __syncthreads();  // all warps' col atomics done
        for (int j = threadIdx.x; j < cnt; j += TPB)
            g_colmin[xc][b][base + j] = s_cmin[j];
    }
    #pragma unroll
    for (int k = 0; k < QPT; k++) {
        int qi = q0 + k * TPB;
        if (qi < N) g_rowmin[zs][b][qi] = best[k] + qn[k];
    }
}

// grid: (RCHUNK, B, 2). dir0: rows (min over SPLIT slots, validity mask,
// sum + count). dir1: cols (min over n-chunk slots, sum). Private slots.
__global__ __launch_bounds__(256) void reduce_kernel(const float* __restrict__ fg,
                                                     int N, int M, int nxc) {
    const int RT = 256;
    int chunk = blockIdx.x, b = blockIdx.y, dir = blockIdx.z;
    int Nq  = dir ? M : N;
    int per = (Nq + RCHUNK - 1) / RCHUNK;
    int qs  = chunk * per;
    int qe  = min(qs + per, Nq);

    float sum = 0.f, cntv = 0.f;
    if (dir == 0) {
        for (int qi = qs + threadIdx.x; qi < qe; qi += RT) {
            float m = g_rowmin[0][b][qi];
            #pragma unroll
            for (int s = 1; s < SPLIT; s++) m = fminf(m, g_rowmin[s][b][qi]);
            m = fmaxf(m, 0.f);
            if (fg[((size_t)b * N + qi) * 3] != PADV) { sum += m; cntv += 1.f; }
        }
    } else {
        for (int mi = qs + threadIdx.x; mi < qe; mi += RT) {
            unsigned u = g_colmin[0][b][mi];
            for (int x = 1; x < nxc; x++) u = min(u, g_colmin[x][b][mi]);
            sum += fmaxf(__uint_as_float(u), 0.f);
        }
    }
    #pragma unroll
    for (int o = 16; o > 0; o >>= 1) {
        sum  += __shfl_xor_sync(0xFFFFFFFFu, sum,  o);
        cntv += __shfl_xor_sync(0xFFFFFFFFu, cntv, o);
    }
    __shared__ float ws[RT / 32][2];
    int wid = threadIdx.x / 32, lane = threadIdx.x % 32;
    if (lane == 0) { ws[wid][0] = sum; ws[wid][1] = cntv; }
    __syncthreads();
    if (threadIdx.x == 0) {
        float ts = 0.f, tc = 0.f;
        for (int w = 0; w < RT / 32; w++) { ts += ws[w][0]; tc += ws[w][1]; }
        g_rsum[dir][b][chunk] = ts;
        if (dir == 0) g_rcnt[b][chunk] = tc;
    }
}

__global__ void final_kernel(float* out, int M, int B) {
    float v = 0.f;
    if (threadIdx.x < B) {
        int b = threadIdx.x;
        float sx = 0.f, sy = 0.f, c = 0.f;
        #pragma unroll
        for (int ch = 0; ch < RCHUNK; ch++) {
            sx += g_rsum[0][b][ch];
            sy += g_rsum[1][b][ch];
            c  += g_rcnt[b][ch];
        }
        v = sx / c + sy / (float)M;
    }
    #pragma unroll
    for (int o = 16; o > 0; o >>= 1) v += __shfl_xor_sync(0xFFFFFFFFu, v, o);
    if (threadIdx.x == 0) out[0] = v / (float)B;
}

extern "C" void kernel_launch(void* const* d_in, const int* in_sizes, int n_in,
                              void* d_out, int out_size) {
    const float* fg  = (const float*)d_in[0];
    const float* prj = (const float*)d_in[1];
    int B = in_sizes[2];
    int N = in_sizes[0] / (3 * B);
    int M = in_sizes[1] / (3 * B);
    float* out = (float*)d_out;

    int nxc = (N + QPB - 1) / QPB;   // n-chunks (4 for N=4096)
    dim3 g(nxc, B, SPLIT);
    nn_fused<<<g, TPB>>>(fg, prj, N, M);
    reduce_kernel<<<dim3(RCHUNK, B, 2), 256>>>(fg, N, M, nxc);
    final_kernel<<<1, 32>>>(out, M, B);
}

// round 6
// speedup vs baseline: 1.0654x; 1.0654x over previous
#include <cuda_runtime.h>

// ChamferDistanceLoss: two-pass NN-min, f32x2 FFMA chain (12 FFMA2 per warp-j
// covering 256 pairs; fma-pipe floor 42.5K cyc/SMSP). This round: kill the
// block-start LDG batch (coalesced float4 staging -> MLP_p1 6) and launch one
// exact reg-capped wave (1184 = 148 SMs x 8 blocks).

#define PADV  10000.0f
#define TPB   128
#define QPT   8            // queries per thread (4 packed f32x2 pairs)
#define QPB   (TPB * QPT)  // 1024 queries per block
#define TILE  128
#define MAXB  8
#define MAXQ  4096
#define MAXS  32
#define RCHUNK 8

static __device__ float g_pmin[2][MAXS][MAXB][MAXQ];   // partial row mins, private slots
static __device__ float g_rsum[2][MAXB][RCHUNK];
static __device__ float g_rcnt[MAXB][RCHUNK];

__device__ __forceinline__ unsigned long long ffma2(unsigned long long a,
                                                    unsigned long long b,
                                                    unsigned long long c) {
    unsigned long long d;
    asm("fma.rn.f32x2 %0, %1, %2, %3;" : "=l"(d) : "l"(a), "l"(b), "l"(c));
    return d;
}
__device__ __forceinline__ unsigned long long pack2(float lo, float hi) {
    unsigned long long d;
    asm("mov.b64 %0, {%1, %2};" : "=l"(d) : "f"(lo), "f"(hi));
    return d;
}
__device__ __forceinline__ void unpack2(unsigned long long v, float& lo, float& hi) {
    asm("mov.b64 {%0, %1}, %2;" : "=f"(lo), "=f"(hi) : "l"(v));
}

// grid: (ceil(maxq/QPB), B, S0+S1). z < S0: dir0 (fg->prj), else dir1.
__global__ __launch_bounds__(TPB, 8) void nn_kernel(const float* __restrict__ fg,
                                                    const float* __restrict__ prj,
                                                    int N, int M, int S0, int S1) {
    __shared__ __align__(16) char s_mem[QPB * 3 * 4];   // 12KB: stage, then tiles

    int z   = blockIdx.z;
    int dir = (z >= S0) ? 1 : 0;
    int zs  = dir ? z - S0 : z;
    int S   = dir ? S1 : S0;
    int b   = blockIdx.y;
    const float* q = dir ? prj : fg;
    const float* r = dir ? fg  : prj;
    int Nq = dir ? M : N;
    int Nr = dir ? N : M;
    int qbase = blockIdx.x * QPB;
    if (qbase >= Nq) return;
    int navail = min(QPB, Nq - qbase);

    // ---- stage query chunk into shared, coalesced float4 (MLP_p1 ~ 6) ----
    float* stage = (float*)s_mem;
    const float* qsrc = q + ((size_t)b * Nq + qbase) * 3;
    int tot = navail * 3;
    if ((((unsigned long long)qsrc) & 15ull) == 0) {
        int nv = tot >> 2;
        const float4* v4 = (const float4*)qsrc;
        for (int i = threadIdx.x; i < nv; i += TPB) ((float4*)stage)[i] = v4[i];
        for (int i = (nv << 2) + threadIdx.x; i < tot; i += TPB) stage[i] = qsrc[i];
    } else {
        for (int i = threadIdx.x; i < tot; i += TPB) stage[i] = qsrc[i];
    }
    __syncthreads();

    // ---- per-thread: 8 queries -> 4 packed f32x2 triples ----
    float qx[QPT], qy[QPT], qz[QPT], qn[QPT];
    bool qok[QPT];
    #pragma unroll
    for (int k = 0; k < QPT; k++) {
        int li = threadIdx.x + k * TPB;
        qok[k] = li < navail;
        int lc = qok[k] ? li : 0;
        qx[k] = stage[lc * 3 + 0];
        qy[k] = stage[lc * 3 + 1];
        qz[k] = stage[lc * 3 + 2];
        qn[k] = qx[k]*qx[k] + qy[k]*qy[k] + qz[k]*qz[k];
    }
    unsigned long long ax[4], ay[4], az[4];
    #pragma unroll
    for (int j = 0; j < 4; j++) {
        ax[j] = pack2(qx[2*j], qx[2*j+1]);
        ay[j] = pack2(qy[2*j], qy[2*j+1]);
        az[j] = pack2(qz[2*j], qz[2*j+1]);
    }

    float best[QPT];
    #pragma unroll
    for (int k = 0; k < QPT; k++) best[k] = 3.0e38f;

    // ---- reference slice for this z ----
    int len = (Nr + S - 1) / S;
    int r0  = zs * len;
    int r1  = min(r0 + len, Nr);
    const float* rb = r + (size_t)b * Nr * 3;
    unsigned long long (*s_tile)[4] = (unsigned long long (*)[4])s_mem;

    for (int base = r0; base < r1; base += TILE) {
        int cnt = min(TILE, r1 - base);
        __syncthreads();   // previous readers done (incl. stage reads, 1st iter)
        if (threadIdx.x < cnt) {
            const float* pp = rb + (size_t)(base + threadIdx.x) * 3;
            float px = pp[0], py = pp[1], pz = pp[2];
            float w = px*px + py*py + pz*pz;
            s_tile[threadIdx.x][0] = pack2(-2.f*px, -2.f*px);
            s_tile[threadIdx.x][1] = pack2(-2.f*py, -2.f*py);
            s_tile[threadIdx.x][2] = pack2(-2.f*pz, -2.f*pz);
            s_tile[threadIdx.x][3] = pack2(w, w);
        }
        __syncthreads();
        #pragma unroll 4
        for (int j = 0; j < cnt; j++) {
            ulonglong2 t01 = *reinterpret_cast<const ulonglong2*>(&s_tile[j][0]);
            ulonglong2 t23 = *reinterpret_cast<const ulonglong2*>(&s_tile[j][2]);
            #pragma unroll
            for (int p2 = 0; p2 < 4; p2++) {
                unsigned long long d = ffma2(t23.x, az[p2], t23.y);
                d = ffma2(t01.y, ay[p2], d);
                d = ffma2(t01.x, ax[p2], d);
                float lo, hi;
                unpack2(d, lo, hi);
                best[2*p2]     = fminf(best[2*p2],     lo);
                best[2*p2 + 1] = fminf(best[2*p2 + 1], hi);
            }
        }
    }
    #pragma unroll
    for (int k = 0; k < QPT; k++) {
        if (qok[k]) g_pmin[dir][zs][b][qbase + threadIdx.x + k * TPB] = best[k] + qn[k];
    }
}

// grid: (RCHUNK, B, 2). Combine split partials, validity + clamp, partial sums.
__global__ __launch_bounds__(256) void reduce_kernel(const float* __restrict__ fg,
                                                     int N, int M, int S0, int S1) {
    const int RT = 256;
    int chunk = blockIdx.x, b = blockIdx.y, dir = blockIdx.z;
    int Nq  = dir ? M : N;
    int S   = dir ? S1 : S0;
    int per = (Nq + RCHUNK - 1) / RCHUNK;
    int qs  = chunk * per;
    int qe  = min(qs + per, Nq);

    float sum = 0.f, cntv = 0.f;
    for (int qi = qs + threadIdx.x; qi < qe; qi += RT) {
        float m = g_pmin[dir][0][b][qi];
        for (int s = 1; s < S; s++) m = fminf(m, g_pmin[dir][s][b][qi]);
        m = fmaxf(m, 0.f);
        if (dir == 0) {
            if (fg[((size_t)b * N + qi) * 3] != PADV) { sum += m; cntv += 1.f; }
        } else {
            sum += m;
        }
    }
    #pragma unroll
    for (int o = 16; o > 0; o >>= 1) {
        sum  += __shfl_xor_sync(0xFFFFFFFFu, sum,  o);
        cntv += __shfl_xor_sync(0xFFFFFFFFu, cntv, o);
    }
    __shared__ float ws[RT / 32][2];
    int wid = threadIdx.x / 32, lane = threadIdx.x % 32;
    if (lane == 0) { ws[wid][0] = sum; ws[wid][1] = cntv; }
    __syncthreads();
    if (threadIdx.x == 0) {
        float ts = 0.f, tc = 0.f;
        for (int w = 0; w < RT / 32; w++) { ts += ws[w][0]; tc += ws[w][1]; }
        g_rsum[dir][b][chunk] = ts;
        if (dir == 0) g_rcnt[b][chunk] = tc;
    }
}

__global__ void final_kernel(float* out, int M, int B) {
    float v = 0.f;
    if (threadIdx.x < B) {
        int b = threadIdx.x;
        float sx = 0.f, sy = 0.f, c = 0.f;
        #pragma unroll
        for (int ch = 0; ch < RCHUNK; ch++) {
            sx += g_rsum[0][b][ch];
            sy += g_rsum[1][b][ch];
            c  += g_rcnt[b][ch];
        }
        v = sx / c + sy / (float)M;
    }
    #pragma unroll
    for (int o = 16; o > 0; o >>= 1) v += __shfl_xor_sync(0xFFFFFFFFu, v, o);
    if (threadIdx.x == 0) out[0] = v / (float)B;
}

extern "C" void kernel_launch(void* const* d_in, const int* in_sizes, int n_in,
                              void* d_out, int out_size) {
    const float* fg  = (const float*)d_in[0];
    const float* prj = (const float*)d_in[1];
    int B = in_sizes[2];
    int N = in_sizes[0] / (3 * B);
    int M = in_sizes[1] / (3 * B);
    float* out = (float*)d_out;

    int maxq = (N > M) ? N : M;
    int xc   = (maxq + QPB - 1) / QPB;          // 4 for 4096
    // one exact reg-capped wave: total blocks ~= 148 * 8 = 1184
    int ztot = 1184 / (xc * B);                  // 37 for (4, 8)
    if (ztot < 2) ztot = 2;
    if (ztot > 2 * MAXS) ztot = 2 * MAXS;
    int S0 = (ztot + 1) / 2;                     // 19: fg->prj slices
    int S1 = ztot - S0;                          // 18: prj->fg slices
    if (S1 < 1) { S1 = 1; S0 = ztot - 1; }

    dim3 g(xc, B, S0 + S1);
    nn_kernel<<<g, TPB>>>(fg, prj, N, M, S0, S1);
    reduce_kernel<<<dim3(RCHUNK, B, 2), 256>>>(fg, N, M, S0, S1);
    final_kernel<<<1, 32>>>(out, M, B);
}